// round 5
// baseline (speedup 1.0000x reference)
#include <cuda_runtime.h>
#include <math.h>

#define B_SZ 32
#define H_SZ 16
#define D_SZ 128
#define BLOCK_SIZE 16
#define MAX_BLOCKS 128
#define SCALE 0.08838834764831845f   // 1/sqrt(128)

#define NWARPS 8

__global__ __launch_bounds__(256, 4)
void paged_attn_kernel(const float* __restrict__ q,
                       const float* __restrict__ kc,
                       const float* __restrict__ vc,
                       const int* __restrict__ bt,
                       const int* __restrict__ ctx,
                       float* __restrict__ out)
{
    const int b = blockIdx.x;
    const int h = blockIdx.y;
    const int tid = threadIdx.x;
    const int warp = tid >> 5;
    const int lane = tid & 31;

    __shared__ int   s_bt[MAX_BLOCKS];
    __shared__ float s_q[D_SZ];
    __shared__ float s_m[NWARPS];
    __shared__ float s_l[NWARPS];
    __shared__ float s_acc[NWARPS][D_SZ];

    const int len = ctx[b];

    if (tid < MAX_BLOCKS) s_bt[tid] = bt[b * MAX_BLOCKS + tid];
    if (tid < D_SZ)       s_q[tid]  = q[(b * H_SZ + h) * D_SZ + tid];
    __syncthreads();

    // per-lane query fragment: 4 consecutive floats
    float4 qf = *reinterpret_cast<const float4*>(&s_q[lane * 4]);

    float m = -INFINITY;
    float l = 0.0f;
    float4 acc = make_float4(0.f, 0.f, 0.f, 0.f);

    const long hoff = (long)h * D_SZ;

    int t = warp;
    // unroll-2: tokens t and t+NWARPS
    for (; t + NWARPS < len; t += 2 * NWARPS) {
        int t0 = t, t1 = t + NWARPS;
        long base0 = ((long)s_bt[t0 >> 4] * BLOCK_SIZE + (t0 & (BLOCK_SIZE - 1))) * (H_SZ * D_SZ) + hoff;
        long base1 = ((long)s_bt[t1 >> 4] * BLOCK_SIZE + (t1 & (BLOCK_SIZE - 1))) * (H_SZ * D_SZ) + hoff;

        float4 k0 = reinterpret_cast<const float4*>(kc + base0)[lane];
        float4 k1 = reinterpret_cast<const float4*>(kc + base1)[lane];
        float4 v0 = reinterpret_cast<const float4*>(vc + base0)[lane];
        float4 v1 = reinterpret_cast<const float4*>(vc + base1)[lane];

        float s0 = k0.x * qf.x + k0.y * qf.y + k0.z * qf.z + k0.w * qf.w;
        float s1 = k1.x * qf.x + k1.y * qf.y + k1.z * qf.z + k1.w * qf.w;
        #pragma unroll
        for (int off = 16; off > 0; off >>= 1) {
            s0 += __shfl_xor_sync(0xffffffffu, s0, off);
            s1 += __shfl_xor_sync(0xffffffffu, s1, off);
        }
        s0 *= SCALE;
        s1 *= SCALE;

        float mnew = fmaxf(m, fmaxf(s0, s1));
        float corr = __expf(m - mnew);
        float p0 = __expf(s0 - mnew);
        float p1 = __expf(s1 - mnew);
        l = l * corr + p0 + p1;
        acc.x = acc.x * corr + p0 * v0.x + p1 * v1.x;
        acc.y = acc.y * corr + p0 * v0.y + p1 * v1.y;
        acc.z = acc.z * corr + p0 * v0.z + p1 * v1.z;
        acc.w = acc.w * corr + p0 * v0.w + p1 * v1.w;
        m = mnew;
    }
    // remainder (at most one token for this warp)
    if (t < len) {
        long base0 = ((long)s_bt[t >> 4] * BLOCK_SIZE + (t & (BLOCK_SIZE - 1))) * (H_SZ * D_SZ) + hoff;
        float4 k0 = reinterpret_cast<const float4*>(kc + base0)[lane];
        float4 v0 = reinterpret_cast<const float4*>(vc + base0)[lane];
        float s0 = k0.x * qf.x + k0.y * qf.y + k0.z * qf.z + k0.w * qf.w;
        #pragma unroll
        for (int off = 16; off > 0; off >>= 1)
            s0 += __shfl_xor_sync(0xffffffffu, s0, off);
        s0 *= SCALE;
        float mnew = fmaxf(m, s0);
        float corr = __expf(m - mnew);
        float p0 = __expf(s0 - mnew);
        l = l * corr + p0;
        acc.x = acc.x * corr + p0 * v0.x;
        acc.y = acc.y * corr + p0 * v0.y;
        acc.z = acc.z * corr + p0 * v0.z;
        acc.w = acc.w * corr + p0 * v0.w;
        m = mnew;
    }

    // stash per-warp state
    if (lane == 0) { s_m[warp] = m; s_l[warp] = l; }
    s_acc[warp][lane * 4 + 0] = acc.x;
    s_acc[warp][lane * 4 + 1] = acc.y;
    s_acc[warp][lane * 4 + 2] = acc.z;
    s_acc[warp][lane * 4 + 3] = acc.w;
    __syncthreads();

    // merge warps: threads 0..127 each handle one d
    if (tid < D_SZ) {
        float M = -INFINITY;
        #pragma unroll
        for (int w = 0; w < NWARPS; w++) M = fmaxf(M, s_m[w]);
        float num = 0.f, den = 0.f;
        #pragma unroll
        for (int w = 0; w < NWARPS; w++) {
            float c = __expf(s_m[w] - M);
            num += c * s_acc[w][tid];
            den += c * s_l[w];
        }
        out[(b * H_SZ + h) * D_SZ + tid] = num / den;
    }
}

extern "C" void kernel_launch(void* const* d_in, const int* in_sizes, int n_in,
                              void* d_out, int out_size) {
    const float* q   = (const float*)d_in[0];
    const float* kc  = (const float*)d_in[1];
    const float* vc  = (const float*)d_in[2];
    const int*   bt  = (const int*)d_in[3];
    const int*   ctx = (const int*)d_in[4];
    float* out = (float*)d_out;

    dim3 grid(B_SZ, H_SZ);
    paged_attn_kernel<<<grid, 256>>>(q, kc, vc, bt, ctx, out);
}

// round 9
// speedup vs baseline: 1.2908x; 1.2908x over previous
#include <cuda_runtime.h>
#include <math.h>

#define B_SZ 32
#define H_SZ 16
#define D_SZ 128
#define BLOCK_SIZE 16
#define MAX_BLOCKS 128
#define SCALE 0.08838834764831845f   // 1/sqrt(128)

#define NWARPS 8
#define NSPLIT 8
#define CHUNK  256        // tokens per split; NSPLIT*CHUNK = 2048 = max context

// Split-KV scratch (device globals: allocation-free).
__device__ float g_pm[B_SZ * H_SZ * NSPLIT];            // partial max
__device__ float g_pl[B_SZ * H_SZ * NSPLIT];            // partial sum
__device__ float g_pacc[B_SZ * H_SZ * NSPLIT * D_SZ];   // partial weighted V

__global__ __launch_bounds__(256, 4)
void paged_attn_split_kernel(const float* __restrict__ q,
                             const float* __restrict__ kc,
                             const float* __restrict__ vc,
                             const int* __restrict__ bt,
                             const int* __restrict__ ctx)
{
    const int b = blockIdx.x;
    const int h = blockIdx.y;
    const int s = blockIdx.z;
    const int tid = threadIdx.x;
    const int warp = tid >> 5;
    const int lane = tid & 31;

    const int len = ctx[b];
    const int start = s * CHUNK;
    if (start >= len) return;                 // this split has no work
    const int end = min(start + CHUNK, len);

    __shared__ int   s_bt[CHUNK / BLOCK_SIZE];  // block ids for this chunk
    __shared__ float s_q[D_SZ];
    __shared__ float s_m[NWARPS];
    __shared__ float s_l[NWARPS];
    __shared__ float s_acc[NWARPS][D_SZ];

    // block-table slice for this chunk
    {
        const int blk0 = start / BLOCK_SIZE;
        const int nblk = (end - start + BLOCK_SIZE - 1) / BLOCK_SIZE;
        if (tid < CHUNK / BLOCK_SIZE) {
            s_bt[tid] = (tid < nblk) ? bt[b * MAX_BLOCKS + blk0 + tid] : 0;
        }
    }
    if (tid < D_SZ) s_q[tid] = q[(b * H_SZ + h) * D_SZ + tid];
    __syncthreads();

    float4 qf = *reinterpret_cast<const float4*>(&s_q[lane * 4]);

    float m = -INFINITY;
    float l = 0.0f;
    float4 acc = make_float4(0.f, 0.f, 0.f, 0.f);

    const long hoff = (long)h * D_SZ;

    int t = start + warp;
    for (; t + NWARPS < end; t += 2 * NWARPS) {
        int t0 = t, t1 = t + NWARPS;
        int r0 = t0 - start, r1 = t1 - start;
        long base0 = ((long)s_bt[r0 >> 4] * BLOCK_SIZE + (t0 & (BLOCK_SIZE - 1))) * (H_SZ * D_SZ) + hoff;
        long base1 = ((long)s_bt[r1 >> 4] * BLOCK_SIZE + (t1 & (BLOCK_SIZE - 1))) * (H_SZ * D_SZ) + hoff;

        float4 k0 = reinterpret_cast<const float4*>(kc + base0)[lane];
        float4 k1 = reinterpret_cast<const float4*>(kc + base1)[lane];
        float4 v0 = reinterpret_cast<const float4*>(vc + base0)[lane];
        float4 v1 = reinterpret_cast<const float4*>(vc + base1)[lane];

        float s0 = k0.x * qf.x + k0.y * qf.y + k0.z * qf.z + k0.w * qf.w;
        float s1 = k1.x * qf.x + k1.y * qf.y + k1.z * qf.z + k1.w * qf.w;
        #pragma unroll
        for (int off = 16; off > 0; off >>= 1) {
            s0 += __shfl_xor_sync(0xffffffffu, s0, off);
            s1 += __shfl_xor_sync(0xffffffffu, s1, off);
        }
        s0 *= SCALE;
        s1 *= SCALE;

        float mnew = fmaxf(m, fmaxf(s0, s1));
        float corr = __expf(m - mnew);
        float p0 = __expf(s0 - mnew);
        float p1 = __expf(s1 - mnew);
        l = l * corr + p0 + p1;
        acc.x = acc.x * corr + p0 * v0.x + p1 * v1.x;
        acc.y = acc.y * corr + p0 * v0.y + p1 * v1.y;
        acc.z = acc.z * corr + p0 * v0.z + p1 * v1.z;
        acc.w = acc.w * corr + p0 * v0.w + p1 * v1.w;
        m = mnew;
    }
    if (t < end) {
        int r0 = t - start;
        long base0 = ((long)s_bt[r0 >> 4] * BLOCK_SIZE + (t & (BLOCK_SIZE - 1))) * (H_SZ * D_SZ) + hoff;
        float4 k0 = reinterpret_cast<const float4*>(kc + base0)[lane];
        float4 v0 = reinterpret_cast<const float4*>(vc + base0)[lane];
        float s0 = k0.x * qf.x + k0.y * qf.y + k0.z * qf.z + k0.w * qf.w;
        #pragma unroll
        for (int off = 16; off > 0; off >>= 1)
            s0 += __shfl_xor_sync(0xffffffffu, s0, off);
        s0 *= SCALE;
        float mnew = fmaxf(m, s0);
        float corr = __expf(m - mnew);
        float p0 = __expf(s0 - mnew);
        l = l * corr + p0;
        acc.x = acc.x * corr + p0 * v0.x;
        acc.y = acc.y * corr + p0 * v0.y;
        acc.z = acc.z * corr + p0 * v0.z;
        acc.w = acc.w * corr + p0 * v0.w;
        m = mnew;
    }

    if (lane == 0) { s_m[warp] = m; s_l[warp] = l; }
    s_acc[warp][lane * 4 + 0] = acc.x;
    s_acc[warp][lane * 4 + 1] = acc.y;
    s_acc[warp][lane * 4 + 2] = acc.z;
    s_acc[warp][lane * 4 + 3] = acc.w;
    __syncthreads();

    // merge warps -> per-split partial
    const int pidx = (b * H_SZ + h) * NSPLIT + s;
    if (tid < D_SZ) {
        float M = -INFINITY;
        #pragma unroll
        for (int w = 0; w < NWARPS; w++) M = fmaxf(M, s_m[w]);
        float num = 0.f, den = 0.f;
        #pragma unroll
        for (int w = 0; w < NWARPS; w++) {
            float c = __expf(s_m[w] - M);
            num += c * s_acc[w][tid];
            den += c * s_l[w];
        }
        g_pacc[pidx * D_SZ + tid] = num;
        if (tid == 0) { g_pm[pidx] = M; g_pl[pidx] = den; }
        else if (tid == 1) { /* nothing */ }
    }
    // den is identical across tid (same s_m/s_l) — store once via tid 0 above,
    // but we need g_pl written: do it from tid 0 only (done above).
    if (tid == 0) {
        // already written
    }
}

__global__ __launch_bounds__(128)
void paged_attn_reduce_kernel(const int* __restrict__ ctx,
                              float* __restrict__ out)
{
    const int bh = blockIdx.x;          // b*H + h
    const int b = bh / H_SZ;
    const int d = threadIdx.x;

    const int len = ctx[b];
    const int nsplit = (len + CHUNK - 1) / CHUNK;

    const int pbase = bh * NSPLIT;

    float M = -INFINITY;
    for (int s = 0; s < nsplit; s++) M = fmaxf(M, g_pm[pbase + s]);

    float num = 0.f, den = 0.f;
    for (int s = 0; s < nsplit; s++) {
        float c = __expf(g_pm[pbase + s] - M);
        num += c * g_pacc[(pbase + s) * D_SZ + d];
        den += c * g_pl[pbase + s];
    }
    out[bh * D_SZ + d] = num / den;
}

extern "C" void kernel_launch(void* const* d_in, const int* in_sizes, int n_in,
                              void* d_out, int out_size) {
    const float* q   = (const float*)d_in[0];
    const float* kc  = (const float*)d_in[1];
    const float* vc  = (const float*)d_in[2];
    const int*   bt  = (const int*)d_in[3];
    const int*   ctx = (const int*)d_in[4];
    float* out = (float*)d_out;

    dim3 grid(B_SZ, H_SZ, NSPLIT);
    paged_attn_split_kernel<<<grid, 256>>>(q, kc, vc, bt, ctx);
    paged_attn_reduce_kernel<<<B_SZ * H_SZ, D_SZ>>>(ctx, out);
}

// round 11
// speedup vs baseline: 1.3255x; 1.0268x over previous
#include <cuda_runtime.h>
#include <math.h>

#define B_SZ 32
#define H_SZ 16
#define D_SZ 128
#define BLOCK_SIZE 16
#define MAX_BLOCKS 128
#define SCALE 0.08838834764831845f   // 1/sqrt(128)

#define NWARPS 8
#define NSPLIT 8
#define CHUNK  256        // tokens per split; NSPLIT*CHUNK = 2048 = max context

// Split-KV scratch (device globals: allocation-free).
__device__ float g_pm[B_SZ * H_SZ * NSPLIT];            // partial max
__device__ float g_pl[B_SZ * H_SZ * NSPLIT];            // partial sum
__device__ float g_pacc[B_SZ * H_SZ * NSPLIT * D_SZ];   // partial weighted V

__device__ __forceinline__ float4 ldcs4(const float* p) {
    return __ldcs(reinterpret_cast<const float4*>(p));
}

__global__ __launch_bounds__(256)
void paged_attn_split_kernel(const float* __restrict__ q,
                             const float* __restrict__ kc,
                             const float* __restrict__ vc,
                             const int* __restrict__ bt,
                             const int* __restrict__ ctx)
{
    const int b = blockIdx.x;
    const int h = blockIdx.y;
    const int s = blockIdx.z;
    const int tid = threadIdx.x;
    const int warp = tid >> 5;
    const int lane = tid & 31;

    const int len = ctx[b];
    const int start = s * CHUNK;
    if (start >= len) return;
    const int end = min(start + CHUNK, len);

    __shared__ int   s_bt[CHUNK / BLOCK_SIZE];
    __shared__ float s_q[D_SZ];
    __shared__ float s_m[NWARPS];
    __shared__ float s_l[NWARPS];
    __shared__ float s_acc[NWARPS][D_SZ];

    {
        const int blk0 = start / BLOCK_SIZE;
        const int nblk = (end - start + BLOCK_SIZE - 1) / BLOCK_SIZE;
        if (tid < CHUNK / BLOCK_SIZE)
            s_bt[tid] = (tid < nblk) ? bt[b * MAX_BLOCKS + blk0 + tid] : 0;
    }
    if (tid < D_SZ) s_q[tid] = q[(b * H_SZ + h) * D_SZ + tid];
    __syncthreads();

    float4 qf = *reinterpret_cast<const float4*>(&s_q[lane * 4]);

    float m = -INFINITY;
    float l = 0.0f;
    float4 acc = make_float4(0.f, 0.f, 0.f, 0.f);

    const long hoff = (long)h * D_SZ;
    const int lane4 = lane * 4;

    int t = start + warp;
    // unroll-4: 8 independent 512B loads in flight per warp
    for (; t + 3 * NWARPS < end; t += 4 * NWARPS) {
        int t0 = t, t1 = t + NWARPS, t2 = t + 2 * NWARPS, t3 = t + 3 * NWARPS;
        int r0 = t0 - start, r1 = t1 - start, r2 = t2 - start, r3 = t3 - start;
        long base0 = ((long)s_bt[r0 >> 4] * BLOCK_SIZE + (t0 & 15)) * (H_SZ * D_SZ) + hoff + lane4;
        long base1 = ((long)s_bt[r1 >> 4] * BLOCK_SIZE + (t1 & 15)) * (H_SZ * D_SZ) + hoff + lane4;
        long base2 = ((long)s_bt[r2 >> 4] * BLOCK_SIZE + (t2 & 15)) * (H_SZ * D_SZ) + hoff + lane4;
        long base3 = ((long)s_bt[r3 >> 4] * BLOCK_SIZE + (t3 & 15)) * (H_SZ * D_SZ) + hoff + lane4;

        float4 k0 = ldcs4(kc + base0);
        float4 k1 = ldcs4(kc + base1);
        float4 k2 = ldcs4(kc + base2);
        float4 k3 = ldcs4(kc + base3);
        float4 v0 = ldcs4(vc + base0);
        float4 v1 = ldcs4(vc + base1);
        float4 v2 = ldcs4(vc + base2);
        float4 v3 = ldcs4(vc + base3);

        float s0 = k0.x * qf.x + k0.y * qf.y + k0.z * qf.z + k0.w * qf.w;
        float s1 = k1.x * qf.x + k1.y * qf.y + k1.z * qf.z + k1.w * qf.w;
        float s2 = k2.x * qf.x + k2.y * qf.y + k2.z * qf.z + k2.w * qf.w;
        float s3 = k3.x * qf.x + k3.y * qf.y + k3.z * qf.z + k3.w * qf.w;
        #pragma unroll
        for (int off = 16; off > 0; off >>= 1) {
            s0 += __shfl_xor_sync(0xffffffffu, s0, off);
            s1 += __shfl_xor_sync(0xffffffffu, s1, off);
            s2 += __shfl_xor_sync(0xffffffffu, s2, off);
            s3 += __shfl_xor_sync(0xffffffffu, s3, off);
        }
        s0 *= SCALE; s1 *= SCALE; s2 *= SCALE; s3 *= SCALE;

        float mnew = fmaxf(fmaxf(m, fmaxf(s0, s1)), fmaxf(s2, s3));
        float corr = __expf(m - mnew);
        float p0 = __expf(s0 - mnew);
        float p1 = __expf(s1 - mnew);
        float p2 = __expf(s2 - mnew);
        float p3 = __expf(s3 - mnew);
        l = l * corr + (p0 + p1) + (p2 + p3);
        acc.x = acc.x * corr + p0 * v0.x + p1 * v1.x + p2 * v2.x + p3 * v3.x;
        acc.y = acc.y * corr + p0 * v0.y + p1 * v1.y + p2 * v2.y + p3 * v3.y;
        acc.z = acc.z * corr + p0 * v0.z + p1 * v1.z + p2 * v2.z + p3 * v3.z;
        acc.w = acc.w * corr + p0 * v0.w + p1 * v1.w + p2 * v2.w + p3 * v3.w;
        m = mnew;
    }
    // remainder: up to 3 tokens per warp
    for (; t < end; t += NWARPS) {
        int r0 = t - start;
        long base0 = ((long)s_bt[r0 >> 4] * BLOCK_SIZE + (t & 15)) * (H_SZ * D_SZ) + hoff + lane4;
        float4 k0 = ldcs4(kc + base0);
        float4 v0 = ldcs4(vc + base0);
        float s0 = k0.x * qf.x + k0.y * qf.y + k0.z * qf.z + k0.w * qf.w;
        #pragma unroll
        for (int off = 16; off > 0; off >>= 1)
            s0 += __shfl_xor_sync(0xffffffffu, s0, off);
        s0 *= SCALE;
        float mnew = fmaxf(m, s0);
        float corr = __expf(m - mnew);
        float p0 = __expf(s0 - mnew);
        l = l * corr + p0;
        acc.x = acc.x * corr + p0 * v0.x;
        acc.y = acc.y * corr + p0 * v0.y;
        acc.z = acc.z * corr + p0 * v0.z;
        acc.w = acc.w * corr + p0 * v0.w;
        m = mnew;
    }

    if (lane == 0) { s_m[warp] = m; s_l[warp] = l; }
    s_acc[warp][lane4 + 0] = acc.x;
    s_acc[warp][lane4 + 1] = acc.y;
    s_acc[warp][lane4 + 2] = acc.z;
    s_acc[warp][lane4 + 3] = acc.w;
    __syncthreads();

    const int pidx = (b * H_SZ + h) * NSPLIT + s;
    if (tid < D_SZ) {
        float M = -INFINITY;
        #pragma unroll
        for (int w = 0; w < NWARPS; w++) M = fmaxf(M, s_m[w]);
        float num = 0.f, den = 0.f;
        #pragma unroll
        for (int w = 0; w < NWARPS; w++) {
            float c = __expf(s_m[w] - M);
            num += c * s_acc[w][tid];
            den += c * s_l[w];
        }
        g_pacc[pidx * D_SZ + tid] = num;
        if (tid == 0) { g_pm[pidx] = M; g_pl[pidx] = den; }
    }
}

// One warp per (b,h); lane owns 4 dims (float4). 64 CTAs x 256 threads.
__global__ __launch_bounds__(256)
void paged_attn_reduce_kernel(const int* __restrict__ ctx,
                              float* __restrict__ out)
{
    const int gw = (blockIdx.x * blockDim.x + threadIdx.x) >> 5;  // global warp = bh
    if (gw >= B_SZ * H_SZ) return;
    const int lane = threadIdx.x & 31;
    const int b = gw / H_SZ;

    const int len = ctx[b];
    const int nsplit = (len + CHUNK - 1) / CHUNK;
    const int pbase = gw * NSPLIT;

    float pm[NSPLIT];
    float M = -INFINITY;
    #pragma unroll
    for (int s = 0; s < NSPLIT; s++) {
        pm[s] = (s < nsplit) ? g_pm[pbase + s] : -INFINITY;
        M = fmaxf(M, pm[s]);
    }

    float4 num = make_float4(0.f, 0.f, 0.f, 0.f);
    float den = 0.f;
    const float4* pacc4 = reinterpret_cast<const float4*>(g_pacc);
    #pragma unroll
    for (int s = 0; s < NSPLIT; s++) {
        if (s < nsplit) {
            float c = __expf(pm[s] - M);
            float4 a = pacc4[(pbase + s) * (D_SZ / 4) + lane];
            den += c * g_pl[pbase + s];
            num.x += c * a.x; num.y += c * a.y;
            num.z += c * a.z; num.w += c * a.w;
        }
    }
    float inv = 1.0f / den;
    float4 o = make_float4(num.x * inv, num.y * inv, num.z * inv, num.w * inv);
    reinterpret_cast<float4*>(out)[gw * (D_SZ / 4) + lane] = o;
}

extern "C" void kernel_launch(void* const* d_in, const int* in_sizes, int n_in,
                              void* d_out, int out_size) {
    const float* q   = (const float*)d_in[0];
    const float* kc  = (const float*)d_in[1];
    const float* vc  = (const float*)d_in[2];
    const int*   bt  = (const int*)d_in[3];
    const int*   ctx = (const int*)d_in[4];
    float* out = (float*)d_out;

    dim3 grid(B_SZ, H_SZ, NSPLIT);
    paged_attn_split_kernel<<<grid, 256>>>(q, kc, vc, bt, ctx);

    int nwarp = B_SZ * H_SZ;                       // 512 warps
    int nthreads = 256;
    int nblocks = (nwarp * 32 + nthreads - 1) / nthreads;  // 64
    paged_attn_reduce_kernel<<<nblocks, nthreads>>>(ctx, out);
}